// round 14
// baseline (speedup 1.0000x reference)
#include <cuda_runtime.h>
#include <math_constants.h>

// Problem shape (fixed by setup_inputs)
#define BB 2
#define NN 8192
#define MM 8192
#define FF 128
#define KEEP 4                 // survivors per split per target
#define SPLITS 8
#define LSPLIT (NN / SPLITS)   // 1024 candidates per split
#define BLK1 128               // targets per block in scan kernel
#define NSEL 6                 // approx pre-selection size (exact-rechecked)

// Scratch (no cudaMalloc allowed)
__device__ float4 g_sc[BB * MM * SPLITS];  // approx top-4 scores (desc)
__device__ int4   g_id[BB * MM * SPLITS];  // matching source indices
__device__ float4 g_w [BB * MM];           // normalized weights (w0,w1,w2,-)
__device__ int4   g_i [BB * MM];           // selected indices   (i0,i1,i2,-)

// Reference-matching sum of squares: ((x*x + y*y) + z*z), all rn, no fma
__device__ __forceinline__ float sumsq_ref(float x, float y, float z) {
    return __fadd_rn(__fadd_rn(__fmul_rn(x, x), __fmul_rn(y, y)), __fmul_rn(z, z));
}

// ===========================================================================
// K1: brute-force scan — R13 geometry (27 warps/SM, issue-bound) + warp-vote
// guard so the ~14-op insert chain only issues on the ~51% of candidates
// where some lane actually inserts.
// Approx FMA score s = t.p - |p|^2/2 (max s ~ min d2, within ~2e-7).
// ===========================================================================
__global__ void __launch_bounds__(BLK1) knn_scan(const float* __restrict__ spc,
                                                 const float* __restrict__ tpc) {
    __shared__ float4 tile[LSPLIT];   // 16 KB

    const int b     = blockIdx.z;
    const int split = blockIdx.y;
    const int m     = blockIdx.x * BLK1 + threadIdx.x;
    const int nbase = split * LSPLIT;

    // Stage candidates, folding -0.5*|p|^2
    const float* __restrict__ sp = spc + (size_t)(b * NN + nbase) * 3;
    for (int i = threadIdx.x; i < LSPLIT; i += BLK1) {
        float x = sp[3 * i + 0], y = sp[3 * i + 1], z = sp[3 * i + 2];
        tile[i] = make_float4(x, y, z, -0.5f * sumsq_ref(x, y, z));
    }

    const float* tp = tpc + (size_t)(b * MM + m) * 3;
    const float tx = tp[0], ty = tp[1], tz = tp[2];

    __syncthreads();

    float b0 = -CUDART_INF_F, b1 = -CUDART_INF_F, b2 = -CUDART_INF_F, b3 = -CUDART_INF_F;
    int   i0 = 0, i1 = 0, i2 = 0, i3 = 0;

#pragma unroll 8
    for (int i = 0; i < LSPLIT; ++i) {
        float4 p = tile[i];  // warp-uniform -> smem broadcast
        float  s = __fmaf_rn(p.x, tx, __fmaf_rn(p.y, ty, __fmaf_rn(p.z, tz, p.w)));
        // Warp-uniform vote: skip the insert chain when no lane inserts (~49%)
        if (__any_sync(0xffffffffu, s > b3)) {
            if (s > b3) {
                if (s > b1) {
                    if (s > b0) { b3=b2; i3=i2; b2=b1; i2=i1; b1=b0; i1=i0; b0=s; i0=i; }
                    else        { b3=b2; i3=i2; b2=b1; i2=i1; b1=s; i1=i; }
                } else {
                    if (s > b2) { b3=b2; i3=i2; b2=s; i2=i; }
                    else        { b3=s; i3=i; }
                }
            }
        }
    }

    size_t o = ((size_t)(b * MM + m)) * SPLITS + split;
    g_sc[o] = make_float4(b0, b1, b2, b3);
    g_id[o] = make_int4(nbase + i0, nbase + i1, nbase + i2, nbase + i3);
}

// ===========================================================================
// K2a: select — ONE THREAD per target (kills the 32x redundant warp work).
// Approx-top-6 of the 32 stored survivors by stored score, then EXACT
// reference recheck of those 6:
//   cross = ((x*tx + y*ty) + z*tz) all rn no-fma; d2 = (t2+s2)-(c+c);
//   d = sqrt(max(d2,0)); tie -> lower index (stable top_k).
// Emits normalized ref-rounded weights + indices.
// ===========================================================================
__device__ __forceinline__ bool key_lt(float dA, int iA, float dB, int iB) {
    return (dA < dB) || (dA == dB && iA < iB);
}

__global__ void __launch_bounds__(256) select_kernel(const float* __restrict__ spc,
                                                     const float* __restrict__ tpc) {
    const int t = blockIdx.x * blockDim.x + threadIdx.x;
    if (t >= BB * MM) return;
    const int b = t / MM;
    const int m = t % MM;

    // ---- approx top-6 by stored score ----
    float c0 = -CUDART_INF_F, c1 = -CUDART_INF_F, c2 = -CUDART_INF_F;
    float c3 = -CUDART_INF_F, c4 = -CUDART_INF_F, c5 = -CUDART_INF_F;
    int   j0 = 0, j1 = 0, j2 = 0, j3 = 0, j4 = 0, j5 = 0;

#pragma unroll
    for (int sx = 0; sx < SPLITS; ++sx) {
        size_t o = ((size_t)t) * SPLITS + sx;
        float4 sc = g_sc[o];
        int4   id = g_id[o];
#pragma unroll
        for (int j = 0; j < KEEP; ++j) {
            float s  = (j == 0) ? sc.x : (j == 1) ? sc.y : (j == 2) ? sc.z : sc.w;
            int   ix = (j == 0) ? id.x : (j == 1) ? id.y : (j == 2) ? id.z : id.w;
            if (s > c5) {
                if (s > c2) {
                    if (s > c0)      { c5=c4;j5=j4; c4=c3;j4=j3; c3=c2;j3=j2; c2=c1;j2=j1; c1=c0;j1=j0; c0=s;j0=ix; }
                    else if (s > c1) { c5=c4;j5=j4; c4=c3;j4=j3; c3=c2;j3=j2; c2=c1;j2=j1; c1=s;j1=ix; }
                    else             { c5=c4;j5=j4; c4=c3;j4=j3; c3=c2;j3=j2; c2=s;j2=ix; }
                } else {
                    if (s > c3)      { c5=c4;j5=j4; c4=c3;j4=j3; c3=s;j3=ix; }
                    else if (s > c4) { c5=c4;j5=j4; c4=s;j4=ix; }
                    else             { c5=s;j5=ix; }
                }
            }
        }
    }

    // ---- exact reference recheck of the 6 survivors ----
    const float* tp = tpc + (size_t)t * 3;
    const float tx = tp[0], ty = tp[1], tz = tp[2];
    const float t2 = sumsq_ref(tx, ty, tz);
    const float* __restrict__ sp = spc + (size_t)b * NN * 3;

    float d0 = CUDART_INF_F, d1 = CUDART_INF_F, d2 = CUDART_INF_F;
    int   i0 = 0x7FFFFFFF,  i1 = 0x7FFFFFFF,  i2 = 0x7FFFFFFF;

#pragma unroll
    for (int j = 0; j < NSEL; ++j) {
        int ix = (j == 0) ? j0 : (j == 1) ? j1 : (j == 2) ? j2
               : (j == 3) ? j3 : (j == 4) ? j4 : j5;
        float x = sp[3 * ix + 0], y = sp[3 * ix + 1], z = sp[3 * ix + 2];
        float c  = __fadd_rn(__fadd_rn(__fmul_rn(x, tx), __fmul_rn(y, ty)),
                             __fmul_rn(z, tz));
        float dq = __fsub_rn(__fadd_rn(t2, sumsq_ref(x, y, z)), __fadd_rn(c, c));
        float dd = __fsqrt_rn(fmaxf(dq, 0.0f));
        if (key_lt(dd, ix, d2, i2)) {
            if (key_lt(dd, ix, d0, i0))      { d2=d1; i2=i1; d1=d0; i1=i0; d0=dd; i0=ix; }
            else if (key_lt(dd, ix, d1, i1)) { d2=d1; i2=i1; d1=dd; i1=ix; }
            else                             { d2=dd; i2=ix; }
        }
    }

    // w = 1/(d + 1e-6); weight = w / sum(w), ascending-k order, all rn
    float w0 = __fdiv_rn(1.0f, __fadd_rn(d0, 1e-6f));
    float w1 = __fdiv_rn(1.0f, __fadd_rn(d1, 1e-6f));
    float w2 = __fdiv_rn(1.0f, __fadd_rn(d2, 1e-6f));
    float s  = __fadd_rn(__fadd_rn(w0, w1), w2);
    w0 = __fdiv_rn(w0, s);
    w1 = __fdiv_rn(w1, s);
    w2 = __fdiv_rn(w2, s);

    g_w[t] = make_float4(w0, w1, w2, 0.0f);
    g_i[t] = make_int4(i0, i1, i2, 0);
}

// ===========================================================================
// K2b: gather — warp per target, pure memory: 3 float4 rows + blend + store.
// Ref-rounded blend order identical to the proven recipe (matches jnp.sum).
// ===========================================================================
__global__ void __launch_bounds__(256) gather_kernel(const float* __restrict__ sfeat,
                                                     float* __restrict__ out) {
    const int gwarp = (blockIdx.x * blockDim.x + threadIdx.x) >> 5;
    const int lane  = threadIdx.x & 31;
    const int b     = gwarp / MM;

    float4 w  = g_w[gwarp];   // warp-uniform broadcast
    int4   id = g_i[gwarp];

    const float4* __restrict__ r0 = (const float4*)(sfeat + (size_t)(b * NN + id.x) * FF);
    const float4* __restrict__ r1 = (const float4*)(sfeat + (size_t)(b * NN + id.y) * FF);
    const float4* __restrict__ r2 = (const float4*)(sfeat + (size_t)(b * NN + id.z) * FF);

    float4 v0 = r0[lane];
    float4 v1 = r1[lane];
    float4 v2 = r2[lane];

    float4 o;
    o.x = __fadd_rn(__fadd_rn(__fmul_rn(v0.x, w.x), __fmul_rn(v1.x, w.y)), __fmul_rn(v2.x, w.z));
    o.y = __fadd_rn(__fadd_rn(__fmul_rn(v0.y, w.x), __fmul_rn(v1.y, w.y)), __fmul_rn(v2.y, w.z));
    o.z = __fadd_rn(__fadd_rn(__fmul_rn(v0.z, w.x), __fmul_rn(v1.z, w.y)), __fmul_rn(v2.z, w.z));
    o.w = __fadd_rn(__fadd_rn(__fmul_rn(v0.w, w.x), __fmul_rn(v1.w, w.y)), __fmul_rn(v2.w, w.z));

    float4* op = (float4*)(out + (size_t)gwarp * FF);
    op[lane] = o;
}

// ---------------------------------------------------------------------------
extern "C" void kernel_launch(void* const* d_in, const int* in_sizes, int n_in,
                              void* d_out, int out_size) {
    const float* source_pc   = (const float*)d_in[0];
    const float* target_pc   = (const float*)d_in[1];
    const float* source_feat = (const float*)d_in[2];
    float*       out         = (float*)d_out;

    dim3 g1(MM / BLK1, SPLITS, BB);   // 64 x 8 x 2 = 1024 blocks, 128 thr
    knn_scan<<<g1, BLK1>>>(source_pc, target_pc);

    select_kernel<<<(BB * MM + 255) / 256, 256>>>(source_pc, target_pc);

    gather_kernel<<<(BB * MM) / 8, 256>>>(source_feat, out);
}

// round 15
// speedup vs baseline: 1.0152x; 1.0152x over previous
#include <cuda_runtime.h>
#include <math_constants.h>

// Problem shape (fixed by setup_inputs)
#define BB 2
#define NN 8192
#define MM 8192
#define FF 128
#define KEEP 4                 // survivors per split per target
#define SPLITS 16
#define LSPLIT (NN / SPLITS)   // 512 candidates per split
#define BLK1 128               // targets per block in scan kernel
#define NSEL 6                 // approx pre-selection size (exact-rechecked)

// Scratch (no cudaMalloc allowed)
__device__ float4 g_sc[BB * MM * SPLITS];  // approx top-4 scores (desc)
__device__ int4   g_id[BB * MM * SPLITS];  // matching source indices
__device__ float4 g_w [BB * MM];           // normalized weights (w0,w1,w2,-)
__device__ int4   g_i [BB * MM];           // selected indices   (i0,i1,i2,-)

// Reference-matching sum of squares: ((x*x + y*y) + z*z), all rn, no fma
__device__ __forceinline__ float sumsq_ref(float x, float y, float z) {
    return __fadd_rn(__fadd_rn(__fmul_rn(x, x), __fmul_rn(y, y)), __fmul_rn(z, z));
}

// ===========================================================================
// K1: brute-force scan — R13's proven inner loop (no vote), SPLITS=16 for
// ~55 warps/SM (issue-bound kernel; occupancy buys issue slots).
// Approx FMA score s = t.p - |p|^2/2 (max s ~ min d2, within ~2e-7).
// Keeps approx top-4 (score+index) per split; exact selection in merge.
// ===========================================================================
__global__ void __launch_bounds__(BLK1) knn_scan(const float* __restrict__ spc,
                                                 const float* __restrict__ tpc) {
    __shared__ float4 tile[LSPLIT];   // 8 KB

    const int b     = blockIdx.z;
    const int split = blockIdx.y;
    const int m     = blockIdx.x * BLK1 + threadIdx.x;
    const int nbase = split * LSPLIT;

    // Stage candidates, folding -0.5*|p|^2
    const float* __restrict__ sp = spc + (size_t)(b * NN + nbase) * 3;
    for (int i = threadIdx.x; i < LSPLIT; i += BLK1) {
        float x = sp[3 * i + 0], y = sp[3 * i + 1], z = sp[3 * i + 2];
        tile[i] = make_float4(x, y, z, -0.5f * sumsq_ref(x, y, z));
    }

    const float* tp = tpc + (size_t)(b * MM + m) * 3;
    const float tx = tp[0], ty = tp[1], tz = tp[2];

    __syncthreads();

    float b0 = -CUDART_INF_F, b1 = -CUDART_INF_F, b2 = -CUDART_INF_F, b3 = -CUDART_INF_F;
    int   i0 = 0, i1 = 0, i2 = 0, i3 = 0;

#pragma unroll 8
    for (int i = 0; i < LSPLIT; ++i) {
        float4 p = tile[i];  // warp-uniform -> smem broadcast
        float  s = __fmaf_rn(p.x, tx, __fmaf_rn(p.y, ty, __fmaf_rn(p.z, tz, p.w)));
        if (s > b3) {
            if (s > b1) {
                if (s > b0) { b3=b2; i3=i2; b2=b1; i2=i1; b1=b0; i1=i0; b0=s; i0=i; }
                else        { b3=b2; i3=i2; b2=b1; i2=i1; b1=s; i1=i; }
            } else {
                if (s > b2) { b3=b2; i3=i2; b2=s; i2=i; }
                else        { b3=s; i3=i; }
            }
        }
    }

    size_t o = ((size_t)(b * MM + m)) * SPLITS + split;
    g_sc[o] = make_float4(b0, b1, b2, b3);
    g_id[o] = make_int4(nbase + i0, nbase + i1, nbase + i2, nbase + i3);
}

// ===========================================================================
// K2a: select — ONE THREAD per target. Approx-top-6 of the 64 stored
// survivors by stored score, then EXACT reference recheck of those 6:
//   cross = ((x*tx + y*ty) + z*tz) all rn no-fma; d2 = (t2+s2)-(c+c);
//   d = sqrt(max(d2,0)); tie -> lower index (stable top_k).
// Emits normalized ref-rounded weights + indices.
// ===========================================================================
__device__ __forceinline__ bool key_lt(float dA, int iA, float dB, int iB) {
    return (dA < dB) || (dA == dB && iA < iB);
}

__global__ void __launch_bounds__(256) select_kernel(const float* __restrict__ spc,
                                                     const float* __restrict__ tpc) {
    const int t = blockIdx.x * blockDim.x + threadIdx.x;
    if (t >= BB * MM) return;
    const int b = t / MM;

    // ---- approx top-6 by stored score ----
    float c0 = -CUDART_INF_F, c1 = -CUDART_INF_F, c2 = -CUDART_INF_F;
    float c3 = -CUDART_INF_F, c4 = -CUDART_INF_F, c5 = -CUDART_INF_F;
    int   j0 = 0, j1 = 0, j2 = 0, j3 = 0, j4 = 0, j5 = 0;

#pragma unroll
    for (int sx = 0; sx < SPLITS; ++sx) {
        size_t o = ((size_t)t) * SPLITS + sx;
        float4 sc = g_sc[o];
        int4   id = g_id[o];
#pragma unroll
        for (int j = 0; j < KEEP; ++j) {
            float s  = (j == 0) ? sc.x : (j == 1) ? sc.y : (j == 2) ? sc.z : sc.w;
            int   ix = (j == 0) ? id.x : (j == 1) ? id.y : (j == 2) ? id.z : id.w;
            if (s > c5) {
                if (s > c2) {
                    if (s > c0)      { c5=c4;j5=j4; c4=c3;j4=j3; c3=c2;j3=j2; c2=c1;j2=j1; c1=c0;j1=j0; c0=s;j0=ix; }
                    else if (s > c1) { c5=c4;j5=j4; c4=c3;j4=j3; c3=c2;j3=j2; c2=c1;j2=j1; c1=s;j1=ix; }
                    else             { c5=c4;j5=j4; c4=c3;j4=j3; c3=c2;j3=j2; c2=s;j2=ix; }
                } else {
                    if (s > c3)      { c5=c4;j5=j4; c4=c3;j4=j3; c3=s;j3=ix; }
                    else if (s > c4) { c5=c4;j5=j4; c4=s;j4=ix; }
                    else             { c5=s;j5=ix; }
                }
            }
        }
    }

    // ---- exact reference recheck of the 6 survivors ----
    const float* tp = tpc + (size_t)t * 3;
    const float tx = tp[0], ty = tp[1], tz = tp[2];
    const float t2 = sumsq_ref(tx, ty, tz);
    const float* __restrict__ sp = spc + (size_t)b * NN * 3;

    float d0 = CUDART_INF_F, d1 = CUDART_INF_F, d2 = CUDART_INF_F;
    int   i0 = 0x7FFFFFFF,  i1 = 0x7FFFFFFF,  i2 = 0x7FFFFFFF;

#pragma unroll
    for (int j = 0; j < NSEL; ++j) {
        int ix = (j == 0) ? j0 : (j == 1) ? j1 : (j == 2) ? j2
               : (j == 3) ? j3 : (j == 4) ? j4 : j5;
        float x = sp[3 * ix + 0], y = sp[3 * ix + 1], z = sp[3 * ix + 2];
        float c  = __fadd_rn(__fadd_rn(__fmul_rn(x, tx), __fmul_rn(y, ty)),
                             __fmul_rn(z, tz));
        float dq = __fsub_rn(__fadd_rn(t2, sumsq_ref(x, y, z)), __fadd_rn(c, c));
        float dd = __fsqrt_rn(fmaxf(dq, 0.0f));
        if (key_lt(dd, ix, d2, i2)) {
            if (key_lt(dd, ix, d0, i0))      { d2=d1; i2=i1; d1=d0; i1=i0; d0=dd; i0=ix; }
            else if (key_lt(dd, ix, d1, i1)) { d2=d1; i2=i1; d1=dd; i1=ix; }
            else                             { d2=dd; i2=ix; }
        }
    }

    // w = 1/(d + 1e-6); weight = w / sum(w), ascending-k order, all rn
    float w0 = __fdiv_rn(1.0f, __fadd_rn(d0, 1e-6f));
    float w1 = __fdiv_rn(1.0f, __fadd_rn(d1, 1e-6f));
    float w2 = __fdiv_rn(1.0f, __fadd_rn(d2, 1e-6f));
    float s  = __fadd_rn(__fadd_rn(w0, w1), w2);
    w0 = __fdiv_rn(w0, s);
    w1 = __fdiv_rn(w1, s);
    w2 = __fdiv_rn(w2, s);

    g_w[t] = make_float4(w0, w1, w2, 0.0f);
    g_i[t] = make_int4(i0, i1, i2, 0);
}

// ===========================================================================
// K2b: gather — warp per target, pure memory: 3 float4 rows + blend + store.
// Ref-rounded blend order identical to the proven recipe (matches jnp.sum).
// ===========================================================================
__global__ void __launch_bounds__(256) gather_kernel(const float* __restrict__ sfeat,
                                                     float* __restrict__ out) {
    const int gwarp = (blockIdx.x * blockDim.x + threadIdx.x) >> 5;
    const int lane  = threadIdx.x & 31;
    const int b     = gwarp / MM;

    float4 w  = g_w[gwarp];   // warp-uniform broadcast
    int4   id = g_i[gwarp];

    const float4* __restrict__ r0 = (const float4*)(sfeat + (size_t)(b * NN + id.x) * FF);
    const float4* __restrict__ r1 = (const float4*)(sfeat + (size_t)(b * NN + id.y) * FF);
    const float4* __restrict__ r2 = (const float4*)(sfeat + (size_t)(b * NN + id.z) * FF);

    float4 v0 = r0[lane];
    float4 v1 = r1[lane];
    float4 v2 = r2[lane];

    float4 o;
    o.x = __fadd_rn(__fadd_rn(__fmul_rn(v0.x, w.x), __fmul_rn(v1.x, w.y)), __fmul_rn(v2.x, w.z));
    o.y = __fadd_rn(__fadd_rn(__fmul_rn(v0.y, w.x), __fmul_rn(v1.y, w.y)), __fmul_rn(v2.y, w.z));
    o.z = __fadd_rn(__fadd_rn(__fmul_rn(v0.z, w.x), __fmul_rn(v1.z, w.y)), __fmul_rn(v2.z, w.z));
    o.w = __fadd_rn(__fadd_rn(__fmul_rn(v0.w, w.x), __fmul_rn(v1.w, w.y)), __fmul_rn(v2.w, w.z));

    float4* op = (float4*)(out + (size_t)gwarp * FF);
    op[lane] = o;
}

// ---------------------------------------------------------------------------
extern "C" void kernel_launch(void* const* d_in, const int* in_sizes, int n_in,
                              void* d_out, int out_size) {
    const float* source_pc   = (const float*)d_in[0];
    const float* target_pc   = (const float*)d_in[1];
    const float* source_feat = (const float*)d_in[2];
    float*       out         = (float*)d_out;

    dim3 g1(MM / BLK1, SPLITS, BB);   // 64 x 16 x 2 = 2048 blocks, 128 thr
    knn_scan<<<g1, BLK1>>>(source_pc, target_pc);

    select_kernel<<<(BB * MM + 255) / 256, 256>>>(source_pc, target_pc);

    gather_kernel<<<(BB * MM) / 8, 256>>>(source_feat, out);
}

// round 16
// speedup vs baseline: 1.1944x; 1.1765x over previous
#include <cuda_runtime.h>
#include <math_constants.h>

// Problem shape (fixed by setup_inputs)
#define BB 2
#define NN 8192
#define MM 8192
#define FF 128
#define KEEP 4                 // survivors per split per target
#define SPLITS 8
#define LSPLIT (NN / SPLITS)   // 1024 candidates per split (10-bit local index)
#define IDXMASK 0x3FFu
#define PACKMASK 0xFFFFFC00u
#define BLK1 128               // targets per block in scan kernel
#define NSURV (SPLITS * KEEP)  // 32 survivors per target

// Scratch (no cudaMalloc allowed)
__device__ float4 g_sc[BB * MM * SPLITS];  // packed top-4 scores (idx in low 10 bits)
__device__ float4 g_w [BB * MM];           // normalized weights (w0,w1,w2,-)
__device__ int4   g_i [BB * MM];           // selected indices   (i0,i1,i2,-)

// Reference-matching sum of squares: ((x*x + y*y) + z*z), all rn, no fma
__device__ __forceinline__ float sumsq_ref(float x, float y, float z) {
    return __fadd_rn(__fadd_rn(__fmul_rn(x, x), __fmul_rn(y, y)), __fmul_rn(z, z));
}

// ===========================================================================
// K1: brute-force scan — R13's proven geometry (27 warps/SM, issue-saturated)
// with a fully branchless inner loop: candidate index packed into the low
// 10 mantissa bits of the approx score, top-4 maintained by a 7-op FMNMX
// sorted network. No predication, no SEL chains, no index registers.
// ===========================================================================
__global__ void __launch_bounds__(BLK1) knn_scan(const float* __restrict__ spc,
                                                 const float* __restrict__ tpc) {
    __shared__ float4 tile[LSPLIT];   // 16 KB

    const int b     = blockIdx.z;
    const int split = blockIdx.y;
    const int m     = blockIdx.x * BLK1 + threadIdx.x;
    const int nbase = split * LSPLIT;

    // Stage candidates, folding -0.5*|p|^2
    const float* __restrict__ sp = spc + (size_t)(b * NN + nbase) * 3;
    for (int i = threadIdx.x; i < LSPLIT; i += BLK1) {
        float x = sp[3 * i + 0], y = sp[3 * i + 1], z = sp[3 * i + 2];
        tile[i] = make_float4(x, y, z, -0.5f * sumsq_ref(x, y, z));
    }

    const float* tp = tpc + (size_t)(b * MM + m) * 3;
    const float tx = tp[0], ty = tp[1], tz = tp[2];

    __syncthreads();

    float b0 = -CUDART_INF_F, b1 = -CUDART_INF_F, b2 = -CUDART_INF_F, b3 = -CUDART_INF_F;

#pragma unroll 8
    for (int i = 0; i < LSPLIT; ++i) {
        float4 p = tile[i];  // warp-uniform -> smem broadcast
        float  s = __fmaf_rn(p.x, tx, __fmaf_rn(p.y, ty, __fmaf_rn(p.z, tz, p.w)));
        // pack local index into low 10 bits (single LOP3)
        float spk = __uint_as_float((__float_as_uint(s) & PACKMASK) | (unsigned)i);
        // branchless sorted top-4 (descending) via min/max network
        float t1 = fminf(b0, spk); b0 = fmaxf(b0, spk);
        float t2 = fminf(b1, t1);  b1 = fmaxf(b1, t1);
        float t3 = fminf(b2, t2);  b2 = fmaxf(b2, t2);
        b3 = fmaxf(b3, t3);
    }

    g_sc[((size_t)(b * MM + m)) * SPLITS + split] = make_float4(b0, b1, b2, b3);
}

// ===========================================================================
// K2a: select — ONE THREAD per target. Unpack all 32 survivors and exact-
// recheck EVERY one with the reference key:
//   cross = ((x*tx + y*ty) + z*tz) all rn no-fma; d2 = (t2+s2)-(c+c);
//   d = sqrt(max(d2,0)); tie -> lower index (stable top_k).
// Emits normalized ref-rounded weights + indices.
// ===========================================================================
__device__ __forceinline__ bool key_lt(float dA, int iA, float dB, int iB) {
    return (dA < dB) || (dA == dB && iA < iB);
}

__global__ void __launch_bounds__(64) select_kernel(const float* __restrict__ spc,
                                                    const float* __restrict__ tpc) {
    const int t = blockIdx.x * blockDim.x + threadIdx.x;
    if (t >= BB * MM) return;
    const int b = t / MM;

    const float* tp = tpc + (size_t)t * 3;
    const float tx = tp[0], ty = tp[1], tz = tp[2];
    const float t2 = sumsq_ref(tx, ty, tz);
    const float* __restrict__ sp = spc + (size_t)b * NN * 3;

    float d0 = CUDART_INF_F, d1 = CUDART_INF_F, d2 = CUDART_INF_F;
    int   i0 = 0x7FFFFFFF,  i1 = 0x7FFFFFFF,  i2 = 0x7FFFFFFF;

#pragma unroll
    for (int sx = 0; sx < SPLITS; ++sx) {
        float4 sc = g_sc[((size_t)t) * SPLITS + sx];
#pragma unroll
        for (int j = 0; j < KEEP; ++j) {
            float v  = (j == 0) ? sc.x : (j == 1) ? sc.y : (j == 2) ? sc.z : sc.w;
            int   ix = sx * LSPLIT + (int)(__float_as_uint(v) & IDXMASK);
            float x = sp[3 * ix + 0], y = sp[3 * ix + 1], z = sp[3 * ix + 2];
            // exact reference arithmetic: mul+add cross, rn everywhere
            float c  = __fadd_rn(__fadd_rn(__fmul_rn(x, tx), __fmul_rn(y, ty)),
                                 __fmul_rn(z, tz));
            float dq = __fsub_rn(__fadd_rn(t2, sumsq_ref(x, y, z)), __fadd_rn(c, c));
            float dd = __fsqrt_rn(fmaxf(dq, 0.0f));
            if (key_lt(dd, ix, d2, i2)) {
                if (key_lt(dd, ix, d0, i0))      { d2=d1; i2=i1; d1=d0; i1=i0; d0=dd; i0=ix; }
                else if (key_lt(dd, ix, d1, i1)) { d2=d1; i2=i1; d1=dd; i1=ix; }
                else                             { d2=dd; i2=ix; }
            }
        }
    }

    // w = 1/(d + 1e-6); weight = w / sum(w), ascending-k order, all rn
    float w0 = __fdiv_rn(1.0f, __fadd_rn(d0, 1e-6f));
    float w1 = __fdiv_rn(1.0f, __fadd_rn(d1, 1e-6f));
    float w2 = __fdiv_rn(1.0f, __fadd_rn(d2, 1e-6f));
    float s  = __fadd_rn(__fadd_rn(w0, w1), w2);
    w0 = __fdiv_rn(w0, s);
    w1 = __fdiv_rn(w1, s);
    w2 = __fdiv_rn(w2, s);

    g_w[t] = make_float4(w0, w1, w2, 0.0f);
    g_i[t] = make_int4(i0, i1, i2, 0);
}

// ===========================================================================
// K2b: gather — warp per target, pure memory: 3 float4 rows + blend + store.
// Ref-rounded blend order identical to the proven recipe (matches jnp.sum).
// ===========================================================================
__global__ void __launch_bounds__(256) gather_kernel(const float* __restrict__ sfeat,
                                                     float* __restrict__ out) {
    const int gwarp = (blockIdx.x * blockDim.x + threadIdx.x) >> 5;
    const int lane  = threadIdx.x & 31;
    const int b     = gwarp / MM;

    float4 w  = g_w[gwarp];   // warp-uniform broadcast
    int4   id = g_i[gwarp];

    const float4* __restrict__ r0 = (const float4*)(sfeat + (size_t)(b * NN + id.x) * FF);
    const float4* __restrict__ r1 = (const float4*)(sfeat + (size_t)(b * NN + id.y) * FF);
    const float4* __restrict__ r2 = (const float4*)(sfeat + (size_t)(b * NN + id.z) * FF);

    float4 v0 = r0[lane];
    float4 v1 = r1[lane];
    float4 v2 = r2[lane];

    float4 o;
    o.x = __fadd_rn(__fadd_rn(__fmul_rn(v0.x, w.x), __fmul_rn(v1.x, w.y)), __fmul_rn(v2.x, w.z));
    o.y = __fadd_rn(__fadd_rn(__fmul_rn(v0.y, w.x), __fmul_rn(v1.y, w.y)), __fmul_rn(v2.y, w.z));
    o.z = __fadd_rn(__fadd_rn(__fmul_rn(v0.z, w.x), __fmul_rn(v1.z, w.y)), __fmul_rn(v2.z, w.z));
    o.w = __fadd_rn(__fadd_rn(__fmul_rn(v0.w, w.x), __fmul_rn(v1.w, w.y)), __fmul_rn(v2.w, w.z));

    float4* op = (float4*)(out + (size_t)gwarp * FF);
    op[lane] = o;
}

// ---------------------------------------------------------------------------
extern "C" void kernel_launch(void* const* d_in, const int* in_sizes, int n_in,
                              void* d_out, int out_size) {
    const float* source_pc   = (const float*)d_in[0];
    const float* target_pc   = (const float*)d_in[1];
    const float* source_feat = (const float*)d_in[2];
    float*       out         = (float*)d_out;

    dim3 g1(MM / BLK1, SPLITS, BB);   // 64 x 8 x 2 = 1024 blocks, 128 thr
    knn_scan<<<g1, BLK1>>>(source_pc, target_pc);

    select_kernel<<<(BB * MM + 63) / 64, 64>>>(source_pc, target_pc);

    gather_kernel<<<(BB * MM) / 8, 256>>>(source_feat, out);
}